// round 14
// baseline (speedup 1.0000x reference)
#include <cuda_runtime.h>
#include <cuda_fp16.h>
#include <cuda_bf16.h>

// SparseVoxelEncoder: trilinear interpolation of 8 corner embeddings per point.
// P = 1048576 points, H = 524288 voxels, NEMB = 600000 embeddings, D = 32.
//
// R9: fp16 shadow table (convert ~15.9us fixed tax). R10/R11: 4 lanes/point,
// LDG.128 gathers, lane-split coords -> main 75.8us, but issue=35%, occ=65%,
// no pipe saturated => LATENCY-bound (idx->feats->gather 3-hop chain ~1100cy).
// R12: software pipeline, ITER=4 points per thread:
//   - sampled_idx prefetched at depth 2,
//   - h-dependent loads (point_xyz/point_feats) + sampled_xyz at depth 1,
//   - gathers of point i overlap the prefetches of i+1/i+2.
// Steady-state exposed latency ~ one L2 gather hop instead of the full chain.

#define P_TOTAL   1048576
#define NEMB      600000
#define D_DIM     32
#define NTHREADS  256
#define ITER      4
#define STRIDE    (P_TOTAL / ITER)     // 262144 points per pass

__device__ __align__(16) __half g_vals_h[(size_t)NEMB * D_DIM];  // 38.4 MB

// ---------------- pass 1: fp32 -> fp16 table conversion ----------------
__global__ __launch_bounds__(256)
void k_convert(const float* __restrict__ values)
{
    const int n4 = NEMB * D_DIM / 4;   // 4.8M float4s
    __half2* __restrict__ dst = (__half2*)g_vals_h;
    for (int i = blockIdx.x * 256 + threadIdx.x; i < n4; i += gridDim.x * 256) {
        float4 v = __ldcs(&((const float4*)values)[i]);   // stream reads
        dst[2 * i + 0] = __floats2half2_rn(v.x, v.y);
        dst[2 * i + 1] = __floats2half2_rn(v.z, v.w);     // default writes -> L2
    }
}

// ---------------- pass 2: pipelined trilerp, 4 lanes/point, 4 points/thread --
__global__ __launch_bounds__(NTHREADS)
void sve_trilerp_kernel(const float* __restrict__ sampled_xyz,   // [P,3]
                        const float* __restrict__ point_xyz,     // [H,3]
                        const int*  __restrict__ sampled_idx,    // [P] int32
                        const int*  __restrict__ point_feats,    // [H,8] int32
                        float* __restrict__ out)                 // [P,32]
{
    const int tid    = blockIdx.x * NTHREADS + threadIdx.x;
    const int group0 = tid >> 2;         // first point handled by this 4-lane group
    const int c4     = tid & 3;          // lane's quarter index (0..3)
    const int gbase  = threadIdx.x & 28; // group base lane within warp
    const int comp   = (c4 < 3) ? c4 : 2;
    const int2* __restrict__ pf2 = (const int2*)point_feats;

    // ---- pipeline prologue ----
    // h at depth 2, h-dependent + sampled_xyz at depth 1
    int   h_cur = __ldcs(&sampled_idx[group0]);
    int   h_nxt = __ldcs(&sampled_idx[group0 + STRIDE]);
    float sv_cur = __ldcs(&sampled_xyz[3 * group0 + comp]);
    float pv_cur = __ldg(&point_xyz[3 * h_cur + comp]);
    int2  e_cur  = __ldg(&pf2[(size_t)h_cur * 4 + c4]);

#pragma unroll
    for (int it = 0; it < ITER; ++it) {
        const int p = group0 + it * STRIDE;

        // normalized coordinate for this lane's component (1/VOXEL_SIZE = 4)
        const float pc = (sv_cur - pv_cur) * 4.0f + 0.5f;
        const float p0 = __shfl_sync(0xffffffffu, pc, gbase + 0);
        const float p1 = __shfl_sync(0xffffffffu, pc, gbase + 1);
        const float p2 = __shfl_sync(0xffffffffu, pc, gbase + 2);

        // lane c4 owns corners 2*c4 (z=0) and 2*c4+1 (z=1); bits x=k&4,y=k&2,z=k&1
        const float wx  = (c4 & 2) ? p0 : 1.0f - p0;
        const float wy  = (c4 & 1) ? p1 : 1.0f - p1;
        const float wxy = wx * wy;
        const float w0  = wxy * (1.0f - p2);
        const float w1  = wxy * p2;
        const int   e0  = e_cur.x, e1 = e_cur.y;

        // broadcast (e, w) of all 8 corners within the 4-lane group
        int   ek[8];
        float wk[8];
#pragma unroll
        for (int j = 0; j < 4; ++j) {
            ek[2 * j + 0] = __shfl_sync(0xffffffffu, e0, gbase + j);
            ek[2 * j + 1] = __shfl_sync(0xffffffffu, e1, gbase + j);
            wk[2 * j + 0] = __shfl_sync(0xffffffffu, w0, gbase + j);
            wk[2 * j + 1] = __shfl_sync(0xffffffffu, w1, gbase + j);
        }

        // gather: lane c4 reads 16B (dims 8c4..8c4+7) of each corner row
        const uint4* __restrict__ vrows = (const uint4*)g_vals_h; // row = 4 uint4
        uint4 f[8];
#pragma unroll
        for (int k = 0; k < 8; ++k)
            f[k] = __ldg(&vrows[(size_t)ek[k] * 4 + c4]);

        // ---- prefetch next point while gathers are in flight ----
        if (it + 1 < ITER) {
            const int pn = group0 + (it + 1) * STRIDE;
            sv_cur = __ldcs(&sampled_xyz[3 * pn + comp]);
            pv_cur = __ldg(&point_xyz[3 * h_nxt + comp]);   // h_nxt arrived long ago
            e_cur  = __ldg(&pf2[(size_t)h_nxt * 4 + c4]);
            h_cur  = h_nxt;
            if (it + 2 < ITER)
                h_nxt = __ldcs(&sampled_idx[group0 + (it + 2) * STRIDE]);
        }

        // ---- consume gathers ----
        float acc[8];
#pragma unroll
        for (int d = 0; d < 8; ++d) acc[d] = 0.0f;
#pragma unroll
        for (int k = 0; k < 8; ++k) {
            const float w = wk[k];
            const float2 a  = __half22float2(*(const __half2*)&f[k].x);
            const float2 b  = __half22float2(*(const __half2*)&f[k].y);
            const float2 cc = __half22float2(*(const __half2*)&f[k].z);
            const float2 dd = __half22float2(*(const __half2*)&f[k].w);
            acc[0] = fmaf(w, a.x,  acc[0]);
            acc[1] = fmaf(w, a.y,  acc[1]);
            acc[2] = fmaf(w, b.x,  acc[2]);
            acc[3] = fmaf(w, b.y,  acc[3]);
            acc[4] = fmaf(w, cc.x, acc[4]);
            acc[5] = fmaf(w, cc.y, acc[5]);
            acc[6] = fmaf(w, dd.x, acc[6]);
            acc[7] = fmaf(w, dd.y, acc[7]);
        }

        // write-once output: 2x streaming STG.128, coalesced across the warp
        float4* orow = (float4*)out + (size_t)p * 8 + c4 * 2;
        __stcs(&orow[0], make_float4(acc[0], acc[1], acc[2], acc[3]));
        __stcs(&orow[1], make_float4(acc[4], acc[5], acc[6], acc[7]));
    }
}

extern "C" void kernel_launch(void* const* d_in, const int* in_sizes, int n_in,
                              void* d_out, int out_size)
{
    const float* sampled_xyz = (const float*)d_in[0];
    const float* point_xyz   = (const float*)d_in[1];
    const float* values      = (const float*)d_in[2];
    const int*   sampled_idx = (const int*)d_in[3];
    const int*   point_feats = (const int*)d_in[4];
    float*       out         = (float*)d_out;

    k_convert<<<4096, 256>>>(values);

    // (P/ITER) groups x 4 lanes = 1M threads -> 4096 CTAs
    sve_trilerp_kernel<<<(STRIDE * 4) / NTHREADS, NTHREADS>>>(
        sampled_xyz, point_xyz, sampled_idx, point_feats, out);
}

// round 15
// speedup vs baseline: 1.1195x; 1.1195x over previous
#include <cuda_runtime.h>
#include <cuda_fp16.h>
#include <cuda_bf16.h>

// SparseVoxelEncoder: trilinear interpolation of 8 corner embeddings per point.
// P = 1048576 points, H = 524288 voxels, NEMB = 600000 embeddings, D = 32.
//
// R9: fp16 shadow table (convert ~15.9us fixed tax) -> DRAM unbound.
// R10/R11: 4 lanes/point, LDG.128 gathers, lane-split coords -> main 75.8us,
// L1tex 67.5%, occ 65%, latency-hiding limited by warp count.
// R12 (ITER=4 pipeline) regressed: regs 61 -> occ 44.7%. Reverted.
// R13: R11 kernel + __launch_bounds__(256, 8) -> force 32 regs, 8 CTAs/SM,
// 64 warps theoretical occupancy. More resident warps = higher L1tex feed
// rate, which is the binding resource (~99 wf/warp, 64 of them gathers).

#define P_TOTAL   1048576
#define NEMB      600000
#define D_DIM     32
#define NTHREADS  256

__device__ __align__(16) __half g_vals_h[(size_t)NEMB * D_DIM];  // 38.4 MB

// ---------------- pass 1: fp32 -> fp16 table conversion ----------------
__global__ __launch_bounds__(256)
void k_convert(const float* __restrict__ values)
{
    const int n4 = NEMB * D_DIM / 4;   // 4.8M float4s
    __half2* __restrict__ dst = (__half2*)g_vals_h;
    for (int i = blockIdx.x * 256 + threadIdx.x; i < n4; i += gridDim.x * 256) {
        float4 v = __ldcs(&((const float4*)values)[i]);   // stream reads
        dst[2 * i + 0] = __floats2half2_rn(v.x, v.y);
        dst[2 * i + 1] = __floats2half2_rn(v.z, v.w);     // default writes -> L2
    }
}

// ---------------- pass 2: trilerp, 4 lanes per point, 8 CTAs/SM ----------------
__global__ __launch_bounds__(NTHREADS, 8)
void sve_trilerp_kernel(const float* __restrict__ sampled_xyz,   // [P,3]
                        const float* __restrict__ point_xyz,     // [H,3]
                        const int*  __restrict__ sampled_idx,    // [P] int32
                        const int*  __restrict__ point_feats,    // [H,8] int32
                        float* __restrict__ out)                 // [P,32]
{
    const int tid   = blockIdx.x * NTHREADS + threadIdx.x;
    const int point = tid >> 2;          // 4 lanes per point
    const int c4    = tid & 3;           // lane's quarter index (0..3)
    const int gbase = threadIdx.x & 28;  // group base lane within warp

    // ---- per-point scalars ----
    const int h = __ldcs(&sampled_idx[point]);   // same addr across group

    // lane-split coordinate load: lane c4 loads component min(c4,2).
    const int comp = (c4 < 3) ? c4 : 2;
    const float sv = __ldcs(&sampled_xyz[3 * point + comp]);
    const float pv = __ldg(&point_xyz[3 * h + comp]);
    // normalized coordinate for this lane's component (1/VOXEL_SIZE = 4)
    const float pc = (sv - pv) * 4.0f + 0.5f;

    // broadcast the 3 normalized coords across the 4-lane group
    const float p0 = __shfl_sync(0xffffffffu, pc, gbase + 0);
    const float p1 = __shfl_sync(0xffffffffu, pc, gbase + 1);
    const float p2 = __shfl_sync(0xffffffffu, pc, gbase + 2);

    // lane c4 owns corners k0=2*c4 (z=0) and k0+1 (z=1).
    // corner bits: x = k&4, y = k&2, z = k&1
    const float wx = (c4 & 2) ? p0 : 1.0f - p0;
    const float wy = (c4 & 1) ? p1 : 1.0f - p1;
    const float wxy = wx * wy;
    const float w0 = wxy * (1.0f - p2);
    const float w1 = wxy * p2;

    // corner embedding ids (2 per lane, one int2)
    const int2 e01 = __ldg(&((const int2*)point_feats)[(size_t)h * 4 + c4]);
    const int e0 = e01.x, e1 = e01.y;

    // ---- broadcast (e, w) of all 8 corners within the 4-lane group ----
    int   ek[8];
    float wk[8];
#pragma unroll
    for (int j = 0; j < 4; ++j) {
        ek[2 * j + 0] = __shfl_sync(0xffffffffu, e0, gbase + j);
        ek[2 * j + 1] = __shfl_sync(0xffffffffu, e1, gbase + j);
        wk[2 * j + 0] = __shfl_sync(0xffffffffu, w0, gbase + j);
        wk[2 * j + 1] = __shfl_sync(0xffffffffu, w1, gbase + j);
    }

    // ---- gather: lane c4 reads 16B (8 halves, dims 8c4..8c4+7) per corner ----
    const uint4* __restrict__ vrows = (const uint4*)g_vals_h; // row = 4 uint4
    uint4 f[8];
#pragma unroll
    for (int k = 0; k < 8; ++k)
        f[k] = __ldg(&vrows[(size_t)ek[k] * 4 + c4]);

    float acc[8];
#pragma unroll
    for (int d = 0; d < 8; ++d) acc[d] = 0.0f;

#pragma unroll
    for (int k = 0; k < 8; ++k) {
        const float w = wk[k];
        const float2 a  = __half22float2(*(const __half2*)&f[k].x);
        const float2 b  = __half22float2(*(const __half2*)&f[k].y);
        const float2 cc = __half22float2(*(const __half2*)&f[k].z);
        const float2 dd = __half22float2(*(const __half2*)&f[k].w);
        acc[0] = fmaf(w, a.x,  acc[0]);
        acc[1] = fmaf(w, a.y,  acc[1]);
        acc[2] = fmaf(w, b.x,  acc[2]);
        acc[3] = fmaf(w, b.y,  acc[3]);
        acc[4] = fmaf(w, cc.x, acc[4]);
        acc[5] = fmaf(w, cc.y, acc[5]);
        acc[6] = fmaf(w, dd.x, acc[6]);
        acc[7] = fmaf(w, dd.y, acc[7]);
    }

    // write-once output: 2x streaming STG.128
    float4* orow = (float4*)out + (size_t)point * 8 + c4 * 2;
    __stcs(&orow[0], make_float4(acc[0], acc[1], acc[2], acc[3]));
    __stcs(&orow[1], make_float4(acc[4], acc[5], acc[6], acc[7]));
}

extern "C" void kernel_launch(void* const* d_in, const int* in_sizes, int n_in,
                              void* d_out, int out_size)
{
    const float* sampled_xyz = (const float*)d_in[0];
    const float* point_xyz   = (const float*)d_in[1];
    const float* values      = (const float*)d_in[2];
    const int*   sampled_idx = (const int*)d_in[3];
    const int*   point_feats = (const int*)d_in[4];
    float*       out         = (float*)d_out;

    k_convert<<<4096, 256>>>(values);

    sve_trilerp_kernel<<<(P_TOTAL * 4) / NTHREADS, NTHREADS>>>(
        sampled_xyz, point_xyz, sampled_idx, point_feats, out);
}

// round 17
// speedup vs baseline: 1.1872x; 1.0605x over previous
#include <cuda_runtime.h>
#include <cuda_fp16.h>
#include <cuda_bf16.h>

// SparseVoxelEncoder: trilinear interpolation of 8 corner embeddings per point.
// P = 1048576 points, H = 524288 voxels, NEMB = 600000 embeddings, D = 32.
//
// R9: fp16 shadow table (convert ~15.5us fixed tax) -> DRAM unbound.
// R10/R11: 4 lanes/point, LDG.128 gathers, lane-split coords.
// R13: launch_bounds(256,8) -> 32 regs, occ 86%, main 72.0us, L1tex 74.3%
//      (wavefront ledger ~98 wf/warp: gathers 64, feats 8, xyz 8, stores 16).
// R14: 256-bit output stores (st.global.cs.v8.b32): each lane writes its
//      contiguous 32B chunk in ONE instruction -> warp touches each output
//      line once -> store wavefronts 16 -> 8 (total ~98 -> ~90).

#define P_TOTAL   1048576
#define NEMB      600000
#define D_DIM     32
#define NTHREADS  256

__device__ __align__(16) __half g_vals_h[(size_t)NEMB * D_DIM];  // 38.4 MB

// ---------------- pass 1: fp32 -> fp16 table conversion ----------------
__global__ __launch_bounds__(256)
void k_convert(const float* __restrict__ values)
{
    const int n4 = NEMB * D_DIM / 4;   // 4.8M float4s
    __half2* __restrict__ dst = (__half2*)g_vals_h;
    for (int i = blockIdx.x * 256 + threadIdx.x; i < n4; i += gridDim.x * 256) {
        float4 v = __ldcs(&((const float4*)values)[i]);   // stream reads
        dst[2 * i + 0] = __floats2half2_rn(v.x, v.y);
        dst[2 * i + 1] = __floats2half2_rn(v.z, v.w);     // default writes -> L2
    }
}

// 256-bit streaming store: one instruction covers a lane's full 32B chunk.
__device__ __forceinline__ void stg256_cs(void* p, const float* a)
{
    asm volatile("st.global.cs.v8.b32 [%0], {%1,%2,%3,%4,%5,%6,%7,%8};"
                 :: "l"(p),
                    "r"(__float_as_uint(a[0])), "r"(__float_as_uint(a[1])),
                    "r"(__float_as_uint(a[2])), "r"(__float_as_uint(a[3])),
                    "r"(__float_as_uint(a[4])), "r"(__float_as_uint(a[5])),
                    "r"(__float_as_uint(a[6])), "r"(__float_as_uint(a[7]))
                 : "memory");
}

// ---------------- pass 2: trilerp, 4 lanes per point, 8 CTAs/SM ----------------
__global__ __launch_bounds__(NTHREADS, 8)
void sve_trilerp_kernel(const float* __restrict__ sampled_xyz,   // [P,3]
                        const float* __restrict__ point_xyz,     // [H,3]
                        const int*  __restrict__ sampled_idx,    // [P] int32
                        const int*  __restrict__ point_feats,    // [H,8] int32
                        float* __restrict__ out)                 // [P,32]
{
    const int tid   = blockIdx.x * NTHREADS + threadIdx.x;
    const int point = tid >> 2;          // 4 lanes per point
    const int c4    = tid & 3;           // lane's quarter index (0..3)
    const int gbase = threadIdx.x & 28;  // group base lane within warp

    // ---- per-point scalars ----
    const int h = __ldcs(&sampled_idx[point]);   // same addr across group

    // lane-split coordinate load: lane c4 loads component min(c4,2).
    const int comp = (c4 < 3) ? c4 : 2;
    const float sv = __ldcs(&sampled_xyz[3 * point + comp]);
    const float pv = __ldg(&point_xyz[3 * h + comp]);
    // normalized coordinate for this lane's component (1/VOXEL_SIZE = 4)
    const float pc = (sv - pv) * 4.0f + 0.5f;

    // broadcast the 3 normalized coords across the 4-lane group
    const float p0 = __shfl_sync(0xffffffffu, pc, gbase + 0);
    const float p1 = __shfl_sync(0xffffffffu, pc, gbase + 1);
    const float p2 = __shfl_sync(0xffffffffu, pc, gbase + 2);

    // lane c4 owns corners k0=2*c4 (z=0) and k0+1 (z=1).
    // corner bits: x = k&4, y = k&2, z = k&1
    const float wx = (c4 & 2) ? p0 : 1.0f - p0;
    const float wy = (c4 & 1) ? p1 : 1.0f - p1;
    const float wxy = wx * wy;
    const float w0 = wxy * (1.0f - p2);
    const float w1 = wxy * p2;

    // corner embedding ids (2 per lane, one int2)
    const int2 e01 = __ldg(&((const int2*)point_feats)[(size_t)h * 4 + c4]);
    const int e0 = e01.x, e1 = e01.y;

    // ---- broadcast (e, w) of all 8 corners within the 4-lane group ----
    int   ek[8];
    float wk[8];
#pragma unroll
    for (int j = 0; j < 4; ++j) {
        ek[2 * j + 0] = __shfl_sync(0xffffffffu, e0, gbase + j);
        ek[2 * j + 1] = __shfl_sync(0xffffffffu, e1, gbase + j);
        wk[2 * j + 0] = __shfl_sync(0xffffffffu, w0, gbase + j);
        wk[2 * j + 1] = __shfl_sync(0xffffffffu, w1, gbase + j);
    }

    // ---- gather: lane c4 reads 16B (8 halves, dims 8c4..8c4+7) per corner ----
    const uint4* __restrict__ vrows = (const uint4*)g_vals_h; // row = 4 uint4
    uint4 f[8];
#pragma unroll
    for (int k = 0; k < 8; ++k)
        f[k] = __ldg(&vrows[(size_t)ek[k] * 4 + c4]);

    float acc[8];
#pragma unroll
    for (int d = 0; d < 8; ++d) acc[d] = 0.0f;

#pragma unroll
    for (int k = 0; k < 8; ++k) {
        const float w = wk[k];
        const float2 a  = __half22float2(*(const __half2*)&f[k].x);
        const float2 b  = __half22float2(*(const __half2*)&f[k].y);
        const float2 cc = __half22float2(*(const __half2*)&f[k].z);
        const float2 dd = __half22float2(*(const __half2*)&f[k].w);
        acc[0] = fmaf(w, a.x,  acc[0]);
        acc[1] = fmaf(w, a.y,  acc[1]);
        acc[2] = fmaf(w, b.x,  acc[2]);
        acc[3] = fmaf(w, b.y,  acc[3]);
        acc[4] = fmaf(w, cc.x, acc[4]);
        acc[5] = fmaf(w, cc.y, acc[5]);
        acc[6] = fmaf(w, dd.x, acc[6]);
        acc[7] = fmaf(w, dd.y, acc[7]);
    }

    // write-once output: ONE 256-bit streaming store per lane (32B chunk)
    stg256_cs((float*)out + (size_t)point * 32 + c4 * 8, acc);
}

extern "C" void kernel_launch(void* const* d_in, const int* in_sizes, int n_in,
                              void* d_out, int out_size)
{
    const float* sampled_xyz = (const float*)d_in[0];
    const float* point_xyz   = (const float*)d_in[1];
    const float* values      = (const float*)d_in[2];
    const int*   sampled_idx = (const int*)d_in[3];
    const int*   point_feats = (const int*)d_in[4];
    float*       out         = (float*)d_out;

    k_convert<<<4096, 256>>>(values);

    sve_trilerp_kernel<<<(P_TOTAL * 4) / NTHREADS, NTHREADS>>>(
        sampled_xyz, point_xyz, sampled_idx, point_feats, out);
}